// round 1
// baseline (speedup 1.0000x reference)
#include <cuda_runtime.h>

// PairedKidneyCriticModel: N=4096 GAT critic on a sparse (avg-deg ~32) graph.
// Strategy: exploit exact sparsity of the masked softmax. One 64MB adjacency
// scan builds a transposed bitmask (deterministic via atomicOr); all attention
// is then sparse gathers over ~33 neighbors/node from an L2-resident hw buffer.

#define NN 4096
#define HH 64
#define LL 3
#define NW (NN/32)          // 128 mask words per node
#define SLOPE 0.2f
#define EPSV 1e-5f

// ---- scratch (device globals; no allocation allowed) ----
__device__ unsigned g_bits[NN * NW];    // 2 MB: bit j of row i => edge j->i
__device__ float g_x [NN * HH];         // embedding (residual input)
__device__ float g_h [NN * HH];         // current hidden state
__device__ float g_hw[NN * HH];         // per-layer h @ W
__device__ float g_src[NN];
__device__ float g_dst[NN];
__device__ float g_AB[3 * HH];          // collapsed embedding: A0, A1, B
__device__ float g_part[512];

// ---- 1. zero the bitmask ----
__global__ void k_zero() {
    int gid = blockIdx.x * blockDim.x + threadIdx.x;   // 2048*256 = 524288
    g_bits[gid] = 0u;
}

// ---- 2. scan adjacency, set transposed bits (order-independent => deterministic) ----
__global__ void k_mask(const float* __restrict__ adj) {
    const long total4 = (long)NN * NN / 4;
    for (long idx = (long)blockIdx.x * blockDim.x + threadIdx.x; idx < total4;
         idx += (long)gridDim.x * blockDim.x) {
        float4 v = ((const float4*)adj)[idx];
        long e = idx * 4;
        int j  = (int)(e >> 12);          // source row of adj
        int i0 = (int)(e & (NN - 1));     // dest column
        float vv[4] = {v.x, v.y, v.z, v.w};
        #pragma unroll
        for (int t = 0; t < 4; t++) {
            int i = i0 + t;
            if (vv[t] != 0.0f && i != j)  // diagonal handled as explicit self-loop
                atomicOr(&g_bits[i * NW + (j >> 5)], 1u << (j & 31));
        }
    }
}

// ---- 3. collapse the two embedding Linears: A = w1@w2 (2xH), B = b1@w2 + b2 ----
__global__ void k_ab(const float* __restrict__ w1, const float* __restrict__ b1,
                     const float* __restrict__ w2, const float* __restrict__ b2) {
    int c = threadIdx.x;  // 64 threads
    float a0 = 0.f, a1 = 0.f, bb = 0.f;
    for (int h = 0; h < HH; h++) {
        float w = w2[h * HH + c];
        a0 += w1[h] * w;
        a1 += w1[HH + h] * w;
        bb += b1[h] * w;
    }
    g_AB[c] = a0; g_AB[HH + c] = a1; g_AB[2 * HH + c] = bb + b2[c];
}

// ---- 4. node embedding ----
__global__ void k_embed(const int* __restrict__ tsp, const float* __restrict__ arr,
                        const float* __restrict__ dep, const float* __restrict__ hard) {
    int gid = blockIdx.x * blockDim.x + threadIdx.x;   // N*H threads
    int i = gid >> 6, c = gid & 63;
    int raw = tsp[0];
    // robust scalar decode: small int pattern => int32, else it's float32 bits
    float ts = (raw > -1000000 && raw < 1000000) ? (float)raw : __int_as_float(raw);
    float p = (ts - arr[i]) / (dep[i] - arr[i]);
    g_x[gid] = p * g_AB[c] + hard[i] * g_AB[HH + c] + g_AB[2 * HH + c];
}

// ---- 5. per-layer: hw = h @ W[l]; src = hw@asrc; dst = hw@adst ----
__global__ void k_gemm(const float* __restrict__ gw, const float* __restrict__ gas,
                       const float* __restrict__ gad, int l) {
    __shared__ float Ws[HH * HH];     // 16 KB
    __shared__ float hs[16 * HH];     // 4 KB (16 rows per block)
    const float* __restrict__ in = (l == 0) ? g_x : g_h;
    const float* __restrict__ W  = gw + l * HH * HH;
    const float* __restrict__ as = gas + l * HH;
    const float* __restrict__ ad = gad + l * HH;
    int tid = threadIdx.x;            // 256
    int rbase = blockIdx.x * 16;      // 256 blocks
    #pragma unroll
    for (int t = 0; t < 16; t++) Ws[t * 256 + tid] = W[t * 256 + tid];
    #pragma unroll
    for (int t = 0; t < 4; t++) hs[t * 256 + tid] = in[rbase * HH + t * 256 + tid];
    __syncthreads();

    int r  = tid >> 4;                // row within block (0..15)
    int c4 = (tid & 15) * 4;          // 4 consecutive output columns
    float4 acc = make_float4(0.f, 0.f, 0.f, 0.f);
    #pragma unroll
    for (int k = 0; k < HH; k++) {
        float hv = hs[r * HH + k];                       // LDS broadcast
        float4 wv = *(const float4*)&Ws[k * HH + c4];    // LDS.128
        acc.x += hv * wv.x; acc.y += hv * wv.y;
        acc.z += hv * wv.z; acc.w += hv * wv.w;
    }
    int row = rbase + r;
    *(float4*)&g_hw[row * HH + c4] = acc;

    float ps = acc.x * as[c4] + acc.y * as[c4 + 1] + acc.z * as[c4 + 2] + acc.w * as[c4 + 3];
    float pd = acc.x * ad[c4] + acc.y * ad[c4 + 1] + acc.z * ad[c4 + 2] + acc.w * ad[c4 + 3];
    #pragma unroll
    for (int off = 8; off; off >>= 1) {
        ps += __shfl_down_sync(0xffffffffu, ps, off, 16);
        pd += __shfl_down_sync(0xffffffffu, pd, off, 16);
    }
    if ((tid & 15) == 0) { g_src[row] = ps; g_dst[row] = pd; }
}

// ---- 6. sparse attention with online softmax: one warp per destination node ----
__global__ void k_attn(const float* __restrict__ gb, int l) {
    int warp = threadIdx.x >> 5, lane = threadIdx.x & 31;
    int i = blockIdx.x * 8 + warp;                      // 512 blocks x 8 warps
    const float* __restrict__ b = gb + l * HH;
    float di = g_dst[i];

    // self-loop initializes running state: weight exp(e_self - m) = 1, s = 1
    float e0 = g_src[i] + di; e0 = (e0 >= 0.f) ? e0 : SLOPE * e0;
    float m = e0, s = 1.0f;
    float2 acc = *(const float2*)&g_hw[i * HH + 2 * lane];

    const unsigned* __restrict__ bm = &g_bits[i * NW];
    for (int w = 0; w < NW; w++) {
        unsigned bits = bm[w];                           // uniform across warp
        while (bits) {
            int bpos = __ffs(bits) - 1;
            bits &= bits - 1;
            int j = w * 32 + bpos;                       // fixed ascending order
            float ej = g_src[j] + di; ej = (ej >= 0.f) ? ej : SLOPE * ej;
            float mn = fmaxf(m, ej);
            float wo = __expf(m - mn);
            float wn = __expf(ej - mn);
            s = s * wo + wn;
            float2 hv = *(const float2*)&g_hw[j * HH + 2 * lane];
            acc.x = acc.x * wo + wn * hv.x;
            acc.y = acc.y * wo + wn * hv.y;
            m = mn;
        }
    }
    float inv = 1.0f / s;
    float v0 = acc.x * inv + b[2 * lane];
    float v1 = acc.y * inv + b[2 * lane + 1];
    if (l < LL - 1) { v0 = fmaxf(v0, 0.f); v1 = fmaxf(v1, 0.f); }
    *(float2*)&g_h[i * HH + 2 * lane] = make_float2(v0, v1);
}

// ---- 7. residual + layernorm + value head dot, per-block partial sums ----
__global__ void k_final(const float* __restrict__ vw) {
    __shared__ float sacc[8];
    int warp = threadIdx.x >> 5, lane = threadIdx.x & 31;
    int i = blockIdx.x * 8 + warp;                      // 512 blocks
    float2 xv = *(const float2*)&g_x[i * HH + 2 * lane];
    float2 hv = *(const float2*)&g_h[i * HH + 2 * lane];
    float v0 = xv.x + hv.x, v1 = xv.y + hv.y;

    float sm = v0 + v1;
    #pragma unroll
    for (int off = 16; off; off >>= 1) sm += __shfl_xor_sync(0xffffffffu, sm, off);
    float mu = sm * (1.0f / 64.0f);
    float d0 = v0 - mu, d1 = v1 - mu;
    float vs = d0 * d0 + d1 * d1;
    #pragma unroll
    for (int off = 16; off; off >>= 1) vs += __shfl_xor_sync(0xffffffffu, vs, off);
    float rstd = rsqrtf(vs * (1.0f / 64.0f) + EPSV);
    float yr = d0 * rstd * vw[2 * lane] + d1 * rstd * vw[2 * lane + 1];
    #pragma unroll
    for (int off = 16; off; off >>= 1) yr += __shfl_xor_sync(0xffffffffu, yr, off);
    if (lane == 0) sacc[warp] = yr;
    __syncthreads();
    if (threadIdx.x == 0) {
        float t = 0.f;
        #pragma unroll
        for (int w = 0; w < 8; w++) t += sacc[w];       // fixed order => deterministic
        g_part[blockIdx.x] = t;
    }
}

// ---- 8. final deterministic reduction + value head ----
__global__ void k_out(const float* __restrict__ vb, float* __restrict__ out) {
    __shared__ float sm[512];
    sm[threadIdx.x] = g_part[threadIdx.x];
    __syncthreads();
    #pragma unroll
    for (int off = 256; off; off >>= 1) {
        if (threadIdx.x < off) sm[threadIdx.x] += sm[threadIdx.x + off];
        __syncthreads();
    }
    if (threadIdx.x == 0)
        out[0] = fmaxf(0.0f, sm[0] * (1.0f / NN) + vb[0]);
}

extern "C" void kernel_launch(void* const* d_in, const int* in_sizes, int n_in,
                              void* d_out, int out_size) {
    const float* adj  = (const float*)d_in[0];
    const int*   ts   = (const int*)  d_in[1];
    const float* arr  = (const float*)d_in[2];
    const float* dep  = (const float*)d_in[3];
    const float* hard = (const float*)d_in[4];
    // d_in[5] = active_agents (all ones, unused by reference math)
    const float* w1 = (const float*)d_in[6];
    const float* b1 = (const float*)d_in[7];
    const float* w2 = (const float*)d_in[8];
    const float* b2 = (const float*)d_in[9];
    const float* gw  = (const float*)d_in[10];
    const float* gas = (const float*)d_in[11];
    const float* gad = (const float*)d_in[12];
    const float* gb  = (const float*)d_in[13];
    const float* vw  = (const float*)d_in[14];
    const float* vb  = (const float*)d_in[15];
    float* out = (float*)d_out;

    k_zero <<<2048, 256>>>();
    k_mask <<<2048, 256>>>(adj);
    k_ab   <<<1, 64>>>(w1, b1, w2, b2);
    k_embed<<<NN * HH / 256, 256>>>(ts, arr, dep, hard);
    for (int l = 0; l < LL; l++) {
        k_gemm<<<NN / 16, 256>>>(gw, gas, gad, l);
        k_attn<<<NN / 8, 256>>>(gb, l);
    }
    k_final<<<NN / 8, 256>>>(vw);
    k_out  <<<1, 512>>>(vb, out);
}

// round 2
// speedup vs baseline: 1.6000x; 1.6000x over previous
#include <cuda_runtime.h>

// PairedKidneyCriticModel: sparse GAT critic, N=4096, H=64, L=3, avg-deg ~33.
// R2: bitmask -> compact neighbor lists (built once), two-phase softmax
// attention, fused prep (nbr+embed+collapsed-embedding), fused final reduce.

#define NN 4096
#define HH 64
#define LL 3
#define NW (NN/32)          // 128 mask words per node
#define MAXD 256            // degree cap (mean 33, max ~65; 256 is ultra-safe)
#define SLOPE 0.2f
#define EPSV 1e-5f

// ---- scratch (device globals; no allocation allowed) ----
__device__ unsigned g_bits[NN * NW];     // 2 MB transposed adjacency bits
__device__ unsigned short g_nbr[NN * MAXD]; // 2 MB neighbor indices (ascending)
__device__ int g_deg[NN];
__device__ float g_x [NN * HH];          // embedding (residual input)
__device__ float g_h [NN * HH];          // hidden state
__device__ float g_hw[NN * HH];          // h @ W (L2-resident, 1 MB)
__device__ float g_src[NN];
__device__ float g_dst[NN];
__device__ float g_part[512];
__device__ int g_cnt;

__device__ __forceinline__ float leaky(float e) { return e >= 0.f ? e : SLOPE * e; }

// ---- 1. scan adjacency, set transposed bits (idempotent atomics => deterministic) ----
__global__ void k_mask(const float* __restrict__ adj) {
    const long total4 = (long)NN * NN / 4;
    for (long idx = (long)blockIdx.x * blockDim.x + threadIdx.x; idx < total4;
         idx += (long)gridDim.x * blockDim.x) {
        float4 v = ((const float4*)adj)[idx];
        long e = idx * 4;
        int j  = (int)(e >> 12);          // source row of adj
        int i0 = (int)(e & (NN - 1));     // dest column
        float vv[4] = {v.x, v.y, v.z, v.w};
        #pragma unroll
        for (int t = 0; t < 4; t++) {
            int i = i0 + t;
            if (vv[t] != 0.0f && i != j)  // diagonal handled as explicit self-loop
                atomicOr(&g_bits[i * NW + (j >> 5)], 1u << (j & 31));
        }
    }
}

// ---- 2. fused prep: blocks [0,512) build neighbor lists; [512,576) embed ----
__global__ void k_prep(const float* __restrict__ w1, const float* __restrict__ b1,
                       const float* __restrict__ w2, const float* __restrict__ b2,
                       const int* __restrict__ tsp, const float* __restrict__ arr,
                       const float* __restrict__ dep, const float* __restrict__ hard) {
    __shared__ float AB[192];
    if (blockIdx.x < 512) {
        // --- neighbor-list compaction: one warp per node, ascending order ---
        int warp = threadIdx.x >> 5, lane = threadIdx.x & 31;
        int i = blockIdx.x * 8 + warp;
        const unsigned* __restrict__ bm = &g_bits[i * NW];
        unsigned short* __restrict__ nb = &g_nbr[i * MAXD];
        int base = 0;
        #pragma unroll
        for (int r = 0; r < 4; r++) {
            unsigned word = bm[r * 32 + lane];
            int cnt = __popc(word);
            int pre = cnt;
            #pragma unroll
            for (int off = 1; off < 32; off <<= 1) {
                int v = __shfl_up_sync(0xffffffffu, pre, off);
                if (lane >= off) pre += v;
            }
            int total = __shfl_sync(0xffffffffu, pre, 31);
            int o = base + pre - cnt;
            while (word) {
                int b = __ffs(word) - 1; word &= word - 1;
                nb[o++] = (unsigned short)(r * 1024 + lane * 32 + b);
            }
            base += total;
        }
        if (lane == 0) g_deg[i] = base;
        if (blockIdx.x == 0 && threadIdx.x == 0) g_cnt = 0;
    } else {
        // --- collapsed embedding: A = w1@w2, B = b1@w2 + b2, then per-node ---
        int t = threadIdx.x;
        if (t < 192) {
            int which = t >> 6, c = t & 63;
            float acc = 0.f;
            for (int h = 0; h < HH; h++) {
                float w = w2[h * HH + c];
                float cf = (which == 0) ? w1[h] : (which == 1 ? w1[HH + h] : b1[h]);
                acc += cf * w;
            }
            if (which == 2) acc += b2[c];
            AB[t] = acc;
        }
        __syncthreads();
        int blk = blockIdx.x - 512;   // 0..63, 64 nodes each
        int raw = tsp[0];
        float ts = (raw > -1000000 && raw < 1000000) ? (float)raw : __int_as_float(raw);
        #pragma unroll
        for (int rep = 0; rep < 16; rep++) {
            int idx = rep * 256 + t;
            int il = idx >> 6, c = idx & 63;
            int i = blk * 64 + il;
            float p = (ts - arr[i]) / (dep[i] - arr[i]);
            g_x[i * HH + c] = p * AB[c] + hard[i] * AB[HH + c] + AB[2 * HH + c];
        }
    }
}

// ---- 3. per-layer: hw = h @ W[l]; src = hw@asrc; dst = hw@adst ----
__global__ void k_gemm(const float* __restrict__ gw, const float* __restrict__ gas,
                       const float* __restrict__ gad, int l) {
    __shared__ float Ws[HH * HH];     // 16 KB
    __shared__ float hs[16 * HH];     // 4 KB
    const float* __restrict__ in = (l == 0) ? g_x : g_h;
    const float* __restrict__ W  = gw + l * HH * HH;
    const float* __restrict__ as = gas + l * HH;
    const float* __restrict__ ad = gad + l * HH;
    int tid = threadIdx.x;            // 256
    int rbase = blockIdx.x * 16;      // 256 blocks
    #pragma unroll
    for (int t = 0; t < 16; t++) Ws[t * 256 + tid] = W[t * 256 + tid];
    #pragma unroll
    for (int t = 0; t < 4; t++) hs[t * 256 + tid] = in[rbase * HH + t * 256 + tid];
    __syncthreads();

    int r  = tid >> 4;
    int c4 = (tid & 15) * 4;
    float4 acc = make_float4(0.f, 0.f, 0.f, 0.f);
    #pragma unroll
    for (int k = 0; k < HH; k++) {
        float hv = hs[r * HH + k];
        float4 wv = *(const float4*)&Ws[k * HH + c4];
        acc.x += hv * wv.x; acc.y += hv * wv.y;
        acc.z += hv * wv.z; acc.w += hv * wv.w;
    }
    int row = rbase + r;
    *(float4*)&g_hw[row * HH + c4] = acc;

    float ps = acc.x * as[c4] + acc.y * as[c4 + 1] + acc.z * as[c4 + 2] + acc.w * as[c4 + 3];
    float pd = acc.x * ad[c4] + acc.y * ad[c4 + 1] + acc.z * ad[c4 + 2] + acc.w * ad[c4 + 3];
    #pragma unroll
    for (int off = 8; off; off >>= 1) {
        ps += __shfl_down_sync(0xffffffffu, ps, off, 16);
        pd += __shfl_down_sync(0xffffffffu, pd, off, 16);
    }
    if ((tid & 15) == 0) { g_src[row] = ps; g_dst[row] = pd; }
}

// ---- 4. sparse attention, two-phase softmax: one warp per destination ----
__global__ void k_attn(const float* __restrict__ gb, int l) {
    __shared__ float         sp[8][MAXD];   // 8 KB: scores then probs
    __shared__ unsigned short sj[8][MAXD];  // 4 KB: neighbor ids
    int warp = threadIdx.x >> 5, lane = threadIdx.x & 31;
    int i = blockIdx.x * 8 + warp;          // 512 blocks x 8 warps
    const float* __restrict__ b = gb + l * HH;
    int deg = g_deg[i];
    float di = g_dst[i];
    float e0 = leaky(g_src[i] + di);        // self-loop score

    // phase A: lane-parallel scoring
    float m = e0;
    const unsigned short* __restrict__ nb = &g_nbr[i * MAXD];
    for (int k = lane; k < deg; k += 32) {
        int j = nb[k];
        sj[warp][k] = (unsigned short)j;
        float e = leaky(g_src[j] + di);
        sp[warp][k] = e;
        m = fmaxf(m, e);
    }
    #pragma unroll
    for (int off = 16; off; off >>= 1) m = fmaxf(m, __shfl_xor_sync(0xffffffffu, m, off));

    float w0 = __expf(e0 - m);
    float sacc = 0.f;
    for (int k = lane; k < deg; k += 32) {
        float p = __expf(sp[warp][k] - m);
        sp[warp][k] = p;
        sacc += p;
    }
    #pragma unroll
    for (int off = 16; off; off >>= 1) sacc += __shfl_xor_sync(0xffffffffu, sacc, off);
    float s = w0 + sacc;
    __syncwarp();

    // phase B: feature-parallel accumulation (fixed ascending order)
    float2 hvs = *(const float2*)&g_hw[i * HH + 2 * lane];
    float2 acc = make_float2(w0 * hvs.x, w0 * hvs.y);
    #pragma unroll 4
    for (int k = 0; k < deg; k++) {
        float p = sp[warp][k];
        int j = sj[warp][k];
        float2 hv = *(const float2*)&g_hw[j * HH + 2 * lane];
        acc.x += p * hv.x;
        acc.y += p * hv.y;
    }
    float inv = 1.0f / s;
    float v0 = acc.x * inv + b[2 * lane];
    float v1 = acc.y * inv + b[2 * lane + 1];
    if (l < LL - 1) { v0 = fmaxf(v0, 0.f); v1 = fmaxf(v1, 0.f); }
    *(float2*)&g_h[i * HH + 2 * lane] = make_float2(v0, v1);
}

// ---- 5. residual + layernorm + value dot + fused global reduce ----
__global__ void k_fin(const float* __restrict__ vw, const float* __restrict__ vb,
                      float* __restrict__ out) {
    __shared__ float sacc[8];
    __shared__ int islast;
    __shared__ float sm[256];
    int warp = threadIdx.x >> 5, lane = threadIdx.x & 31;
    int i = blockIdx.x * 8 + warp;          // 512 blocks
    float2 xv = *(const float2*)&g_x[i * HH + 2 * lane];
    float2 hv = *(const float2*)&g_h[i * HH + 2 * lane];
    float v0 = xv.x + hv.x, v1 = xv.y + hv.y;

    float smv = v0 + v1;
    #pragma unroll
    for (int off = 16; off; off >>= 1) smv += __shfl_xor_sync(0xffffffffu, smv, off);
    float mu = smv * (1.0f / 64.0f);
    float d0 = v0 - mu, d1 = v1 - mu;
    float vs = d0 * d0 + d1 * d1;
    #pragma unroll
    for (int off = 16; off; off >>= 1) vs += __shfl_xor_sync(0xffffffffu, vs, off);
    float rstd = rsqrtf(vs * (1.0f / 64.0f) + EPSV);
    float yr = d0 * rstd * vw[2 * lane] + d1 * rstd * vw[2 * lane + 1];
    #pragma unroll
    for (int off = 16; off; off >>= 1) yr += __shfl_xor_sync(0xffffffffu, yr, off);
    if (lane == 0) sacc[warp] = yr;
    __syncthreads();

    if (threadIdx.x == 0) {
        float t = 0.f;
        #pragma unroll
        for (int w = 0; w < 8; w++) t += sacc[w];
        g_part[blockIdx.x] = t;
        __threadfence();
        islast = (atomicAdd(&g_cnt, 1) == 511);
    }
    __syncthreads();
    if (islast) {
        __threadfence();
        float v = g_part[threadIdx.x] + g_part[threadIdx.x + 256];
        sm[threadIdx.x] = v;
        __syncthreads();
        #pragma unroll
        for (int off = 128; off; off >>= 1) {
            if (threadIdx.x < off) sm[threadIdx.x] += sm[threadIdx.x + off];
            __syncthreads();
        }
        if (threadIdx.x == 0)
            out[0] = fmaxf(0.0f, sm[0] * (1.0f / NN) + vb[0]);
    }
}

extern "C" void kernel_launch(void* const* d_in, const int* in_sizes, int n_in,
                              void* d_out, int out_size) {
    const float* adj  = (const float*)d_in[0];
    const int*   ts   = (const int*)  d_in[1];
    const float* arr  = (const float*)d_in[2];
    const float* dep  = (const float*)d_in[3];
    const float* hard = (const float*)d_in[4];
    const float* w1 = (const float*)d_in[6];
    const float* b1 = (const float*)d_in[7];
    const float* w2 = (const float*)d_in[8];
    const float* b2 = (const float*)d_in[9];
    const float* gw  = (const float*)d_in[10];
    const float* gas = (const float*)d_in[11];
    const float* gad = (const float*)d_in[12];
    const float* gb  = (const float*)d_in[13];
    const float* vw  = (const float*)d_in[14];
    const float* vb  = (const float*)d_in[15];
    float* out = (float*)d_out;

    void* bits_ptr = nullptr;
    cudaGetSymbolAddress(&bits_ptr, g_bits);
    cudaMemsetAsync(bits_ptr, 0, sizeof(unsigned) * NN * NW, 0);

    k_mask<<<2048, 256>>>(adj);
    k_prep<<<576, 256>>>(w1, b1, w2, b2, ts, arr, dep, hard);
    for (int l = 0; l < LL; l++) {
        k_gemm<<<NN / 16, 256>>>(gw, gas, gad, l);
        k_attn<<<NN / 8, 256>>>(gb, l);
    }
    k_fin<<<NN / 8, 256>>>(vw, vb, out);
}